// round 15
// baseline (speedup 1.0000x reference)
#include <cuda_runtime.h>
#include <cuda_bf16.h>
#include <cstdint>

#define BATCH 16
#define CIN   256
#define HH    80
#define WW    80
#define CMID  64
#define K2T   25
#define HO    160
#define WO    160
#define EPS   1e-5f

// ---------------------------------------------------------------------------
// Device scratch (allocation-free)
// ---------------------------------------------------------------------------
__device__ __align__(16) __nv_bfloat16 g_midT_hi[(size_t)BATCH * 6400 * 64]; // [b][pix][c]
__device__ __align__(16) __nv_bfloat16 g_midT_lo[(size_t)BATCH * 6400 * 64];
// per-tap weights, n-major: [tap][split][c(104)][ic(72)] bf16
__device__ __align__(16) __nv_bfloat16 g_weP[9 * 2 * 104 * 72];
__device__ __align__(16) float g_wm[(size_t)BATCH * K2T * HO * WO];
__device__ __align__(16) float g_xT[(size_t)BATCH * 6400 * 256];   // X pixel-major, 105MB

__device__ __forceinline__ uint32_t smem_u32(const void* p) {
    uint32_t a;
    asm("{ .reg .u64 t; cvta.to.shared.u64 t, %1; cvt.u32.u64 %0, t; }" : "=r"(a) : "l"(p));
    return a;
}
__device__ __forceinline__ void ldsm_x4(uint32_t& r0, uint32_t& r1, uint32_t& r2, uint32_t& r3,
                                        uint32_t addr) {
    asm volatile("ldmatrix.sync.aligned.m8n8.x4.shared.b16 {%0,%1,%2,%3}, [%4];"
                 : "=r"(r0), "=r"(r1), "=r"(r2), "=r"(r3) : "r"(addr));
}
__device__ __forceinline__ void ldsm_x2(uint32_t& r0, uint32_t& r1, uint32_t addr) {
    asm volatile("ldmatrix.sync.aligned.m8n8.x2.shared.b16 {%0,%1}, [%2];"
                 : "=r"(r0), "=r"(r1) : "r"(addr));
}
__device__ __forceinline__ void ldsm_x2t(uint32_t& r0, uint32_t& r1, uint32_t addr) {
    asm volatile("ldmatrix.sync.aligned.m8n8.x2.trans.shared.b16 {%0,%1}, [%2];"
                 : "=r"(r0), "=r"(r1) : "r"(addr));
}
__device__ __forceinline__ void mma16816(float* d, const uint32_t* a, uint32_t b0, uint32_t b1) {
    asm volatile(
        "mma.sync.aligned.m16n8k16.row.col.f32.bf16.bf16.f32 "
        "{%0,%1,%2,%3}, {%4,%5,%6,%7}, {%8,%9}, {%0,%1,%2,%3};"
        : "+f"(d[0]), "+f"(d[1]), "+f"(d[2]), "+f"(d[3])
        : "r"(a[0]), "r"(a[1]), "r"(a[2]), "r"(a[3]), "r"(b0), "r"(b1));
}
// Packed fp32 helpers (Blackwell f32x2 pipe)
__device__ __forceinline__ void fma2(uint64_t& d, uint64_t a, uint64_t b) {
    asm("fma.rn.f32x2 %0, %1, %2, %0;" : "+l"(d) : "l"(a), "l"(b));
}
__device__ __forceinline__ uint64_t bcast2(float x) {
    uint64_t r;
    asm("mov.b64 %0, {%1, %1};" : "=l"(r) : "f"(x));
    return r;
}
__device__ __forceinline__ void unpack2(float& lo, float& hi, uint64_t v) {
    asm("mov.b64 {%0, %1}, %2;" : "=f"(lo), "=f"(hi) : "l"(v));
}
__device__ __forceinline__ void lds_v2u64(uint64_t& a, uint64_t& b, uint32_t addr) {
    asm volatile("ld.shared.v2.u64 {%0, %1}, [%2];" : "=l"(a), "=l"(b) : "r"(addr));
}
__device__ __forceinline__ void cp_async16(uint32_t saddr, const void* gptr, uint32_t sz) {
    asm volatile("cp.async.cg.shared.global [%0], [%1], 16, %2;"
                 :: "r"(saddr), "l"(gptr), "r"(sz) : "memory");
}

// ---------------------------------------------------------------------------
// K0: conv2 weights -> [tap][split][c pad 104][ic pad 72] bf16 split
// ---------------------------------------------------------------------------
__global__ __launch_bounds__(256) void k0_wprep(const float* __restrict__ We) {
    int i = blockIdx.x * 256 + threadIdx.x;
    if (i >= 9 * 2 * 104 * 72) return;
    int tap = i / 14976, r = i % 14976;
    int s = r / 7488; r %= 7488;
    int c = r / 72, ic = r % 72;
    float v = (c < 100 && ic < 64) ? We[c * 576 + ic * 9 + tap] : 0.f;
    __nv_bfloat16 hi = __float2bfloat16(v);
    g_weP[i] = s ? __float2bfloat16(v - __bfloat162float(hi)) : hi;
}

// ---------------------------------------------------------------------------
// K1 v4: 1x1 conv (256->64) via mma.sync bf16 split-3 + BN + SiLU.
// Also writes fp32 X transpose g_xT. Prefetch issued BEFORE g_xT writeout.
// ---------------------------------------------------------------------------
#define K1_SW    0            // weights hi [64][528B] = 33792; lo at +33792
#define K1_SXS   67584        // X chunk bf16 [split][32k][272B] = 8704*2
#define K1_SBN   84992        // scs 256B + bis 256B
#define K1_XT32  85504        // fp32 transpose buffer [128px][36f] = 18432B
#define K1_SMEM  103936
#define K1_DT    0            // epilogue [split][128px][144B], reuses weights

__global__ __launch_bounds__(256, 2) void k1_comp(
    const float* __restrict__ X, const float* __restrict__ Wc,
    const float* __restrict__ g1, const float* __restrict__ b1,
    const float* __restrict__ m1, const float* __restrict__ v1)
{
    extern __shared__ __align__(16) char sm1[];
    const int b   = blockIdx.y;
    const int px0 = blockIdx.x * 128;
    const int tid = threadIdx.x;
    const int wid = tid >> 5, lan = tid & 31;
    const uint32_t smb = smem_u32(sm1);

    __nv_bfloat16* Wh = (__nv_bfloat16*)(sm1 + K1_SW);
    __nv_bfloat16* Wl = Wh + 16896;
    for (int i = tid; i < 16384; i += 256) {
        int m = i >> 8, k = i & 255;
        float v = Wc[i];
        __nv_bfloat16 hi = __float2bfloat16(v);
        Wh[m * 264 + k] = hi;
        Wl[m * 264 + k] = __float2bfloat16(v - __bfloat162float(hi));
    }
    float* scs = (float*)(sm1 + K1_SBN);
    float* bis = scs + 64;
    if (tid < 64) {
        float is = g1[tid] * rsqrtf(v1[tid] + EPS);
        scs[tid] = is;
        bis[tid] = b1[tid] - m1[tid] * is;
    }

    const float* Xb = X + (size_t)b * 256 * 6400 + px0;
    __nv_bfloat16* Xh = (__nv_bfloat16*)(sm1 + K1_SXS);
    __nv_bfloat16* Xl = Xh + 4352;
    float* XT = (float*)(sm1 + K1_XT32);

    float xp[16];
#pragma unroll
    for (int j = 0; j < 16; j++) {
        int e = j * 256 + tid;
        xp[j] = Xb[(size_t)(e >> 7) * 6400 + (e & 127)];
    }

    const int warpm = wid & 1;
    const int warpn = wid >> 1;

    float acc[2][4][4];
#pragma unroll
    for (int mb = 0; mb < 2; mb++)
#pragma unroll
        for (int nb = 0; nb < 4; nb++)
#pragma unroll
            for (int j = 0; j < 4; j++) acc[mb][nb][j] = 0.f;

    const uint32_t a_row = (uint32_t)(warpm * 32 + (lan & 15));
    const uint32_t a_half = (uint32_t)((lan >> 4) << 4);
    const uint32_t aw_hi = smb + K1_SW + a_row * 528 + a_half;
    const uint32_t aw_lo = aw_hi + 33792;
    const uint32_t b_base = smb + K1_SXS + (uint32_t)((lan & 15) * 272 + warpn * 64);

#pragma unroll 1
    for (int cg = 0; cg < 8; cg++) {
#pragma unroll
        for (int j = 0; j < 16; j++) {
            int e = j * 256 + tid;
            int kr = e >> 7, px = e & 127;
            float v = xp[j];
            __nv_bfloat16 hi = __float2bfloat16(v);
            Xh[kr * 136 + px] = hi;
            Xl[kr * 136 + px] = __float2bfloat16(v - __bfloat162float(hi));
            XT[px * 36 + kr] = v;
        }
        __syncthreads();

        // prefetch next chunk FIRST (independent LDGs fly during writeout)
        float xn[16];
        if (cg < 7) {
#pragma unroll
            for (int j = 0; j < 16; j++) {
                int e = j * 256 + tid;
                xn[j] = Xb[(size_t)((cg + 1) * 32 + (e >> 7)) * 6400 + (e & 127)];
            }
        }

        // write-out g_xT for this chunk (coalesced float4)
        {
            float* dst = g_xT + ((size_t)(b * 6400 + px0)) * 256 + cg * 32;
            for (int i = tid; i < 1024; i += 256) {
                int px = i >> 3, c4 = i & 7;
                float4 v = *(float4*)&XT[px * 36 + c4 * 4];
                *(float4*)&dst[(size_t)px * 256 + c4 * 4] = v;
            }
        }

        const uint32_t kco = (uint32_t)(cg * 64);
#pragma unroll
        for (int kstep = 0; kstep < 2; kstep++) {
            const uint32_t ko = kco + (uint32_t)(kstep * 32);
            uint32_t Ah[2][4], Al[2][4];
            ldsm_x4(Ah[0][0], Ah[0][1], Ah[0][2], Ah[0][3], aw_hi + ko);
            ldsm_x4(Ah[1][0], Ah[1][1], Ah[1][2], Ah[1][3], aw_hi + 16 * 528 + ko);
            ldsm_x4(Al[0][0], Al[0][1], Al[0][2], Al[0][3], aw_lo + ko);
            ldsm_x4(Al[1][0], Al[1][1], Al[1][2], Al[1][3], aw_lo + 16 * 528 + ko);
            const uint32_t bk = b_base + (uint32_t)(kstep * 16 * 272);
#pragma unroll
            for (int nb = 0; nb < 4; nb++) {
                uint32_t bh0, bh1, bl0, bl1;
                ldsm_x2t(bh0, bh1, bk + (uint32_t)(nb * 16));
                ldsm_x2t(bl0, bl1, bk + 8704 + (uint32_t)(nb * 16));
#pragma unroll
                for (int mb = 0; mb < 2; mb++) {
                    mma16816(acc[mb][nb], Ah[mb], bh0, bh1);
                    mma16816(acc[mb][nb], Ah[mb], bl0, bl1);
                    mma16816(acc[mb][nb], Al[mb], bh0, bh1);
                }
            }
        }
        __syncthreads();
#pragma unroll
        for (int j = 0; j < 16; j++) xp[j] = xn[j];
    }

    __nv_bfloat16* Dh = (__nv_bfloat16*)(sm1 + K1_DT);
    __nv_bfloat16* Dl = Dh + 9216;
#pragma unroll
    for (int mb = 0; mb < 2; mb++) {
#pragma unroll
        for (int nb = 0; nb < 4; nb++) {
            int m = warpm * 32 + mb * 16 + (lan >> 2);
            int p = warpn * 32 + nb * 8 + 2 * (lan & 3);
#pragma unroll
            for (int j = 0; j < 4; j++) {
                int mch = m + (j >> 1) * 8;
                int pp  = p + (j & 1);
                float v = acc[mb][nb][j] * scs[mch] + bis[mch];
                float sv = v / (1.f + __expf(-v));
                __nv_bfloat16 hi = __float2bfloat16(sv);
                Dh[pp * 72 + mch] = hi;
                Dl[pp * 72 + mch] = __float2bfloat16(sv - __bfloat162float(hi));
            }
        }
    }
    __syncthreads();

    for (int i = tid; i < 2048; i += 256) {
        int split = i >> 10, r = (i >> 3) & 127, ch8 = i & 7;
        uint4 v = *(const uint4*)(sm1 + K1_DT + split * 18432 + r * 144 + ch8 * 16);
        uint4* dst = (uint4*)(split ? g_midT_lo : g_midT_hi);
        dst[(size_t)(b * 6400 + px0 + r) * 8 + ch8] = v;
    }
}

// ---------------------------------------------------------------------------
// K2 v4: 3x3 conv via mma.sync bf16 split-3; cp.async for BOTH activations
// and double-buffered weights; ONE sync per tap; x4 B loads.
// ---------------------------------------------------------------------------
#define SM_ACT_HI 0
#define SM_ACT_LO 25920
#define SM_WB0    51840
#define SM_WB1    81792
#define SM_SCS    113472
#define SM_BIS    113872
#define SM_TOTAL  114272
#define WSPLIT    14976
#define DT_STRIDE 122

__global__ __launch_bounds__(256, 2)
void k2_enc(const float* __restrict__ g2, const float* __restrict__ b2,
            const float* __restrict__ m2, const float* __restrict__ v2)
{
    extern __shared__ __align__(16) char sm[];
    const int b  = blockIdx.z;
    const int h0 = blockIdx.y * 16;
    const int w0 = blockIdx.x * 8;
    const int tid = threadIdx.x;
    const int wid = tid >> 5;
    const int lan = tid & 31;
    const uint32_t smb = smem_u32(sm);

    if (tid < 100) {
        float is = g2[tid] * rsqrtf(v2[tid] + EPS);
        ((float*)(sm + SM_SCS))[tid] = is;
        ((float*)(sm + SM_BIS))[tid] = b2[tid] - m2[tid] * is;
    }

    // stage 18x10 activation tile (hi+lo) via cp.async (zfill borders)
    for (int k = tid; k < 2880; k += 256) {
        int bufi = (k >= 1440);
        int r = bufi ? k - 1440 : k;
        int row = r >> 3, ch = r & 7;
        int y = row / 10, x = row - y * 10;
        int gh = h0 + y - 1, gw = w0 + x - 1;
        bool ok = (gh >= 0 && gh < HH && gw >= 0 && gw < WW);
        const uint4* src = (const uint4*)(bufi ? g_midT_lo : g_midT_hi)
                           + (size_t)(b * 6400 + (ok ? (gh * WW + gw) : 0)) * 8 + ch;
        cp_async16(smb + (bufi ? SM_ACT_LO : SM_ACT_HI) + (uint32_t)(row * 144 + (ch << 4)),
                   src, ok ? 16u : 0u);
    }
    asm volatile("cp.async.commit_group;" ::: "memory");

#define K2_WSTAGE(tapx, bufoff) do {                                          \
        const uint4* gsrc = (const uint4*)g_weP + (tapx) * 1872;              \
        for (int k = tid; k < 1872; k += 256)                                 \
            cp_async16(smb + (bufoff) + (uint32_t)(k << 4), gsrc + k, 16);    \
        asm volatile("cp.async.commit_group;" ::: "memory");                  \
    } while (0)

    K2_WSTAGE(0, SM_WB0);

    const int warpm = wid & 3;
    const int warpn = wid >> 2;

    float acc[2][7][4];
#pragma unroll
    for (int mb = 0; mb < 2; mb++)
#pragma unroll
        for (int nb = 0; nb < 7; nb++)
#pragma unroll
            for (int j = 0; j < 4; j++) acc[mb][nb][j] = 0.f;

    const int pA0 = warpm * 32 + (lan & 15);
    const int pyA0 = pA0 >> 3, pxA0 = pA0 & 7;
    const uint32_t a_half = (uint32_t)((lan >> 4) << 4);
    const uint32_t row4 = (uint32_t)((lan & 7) + ((lan >> 4) << 3));
    const uint32_t half4 = (uint32_t)(((lan >> 3) & 1) << 4);
    const uint32_t wb4_off = ((uint32_t)warpn * 56 + row4) * 144 + half4;
    const int cB = warpn * 56 + (lan & 7);
    const uint32_t b_half = (uint32_t)(((lan >> 3) & 1) << 4);
    const uint32_t wb_off = (uint32_t)cB * 144 + b_half;

    for (int tap = 0; tap < 9; tap++) {
        const int dy = tap / 3, dx = tap - dy * 3;
        asm volatile("cp.async.wait_group 0;" ::: "memory");
        __syncthreads();
        if (tap + 1 < 9) {
            if ((tap + 1) & 1) K2_WSTAGE(tap + 1, SM_WB1);
            else               K2_WSTAGE(tap + 1, SM_WB0);
        }

        const uint32_t wbuf = smb + ((tap & 1) ? SM_WB1 : SM_WB0);
        const uint32_t wb4_hi = wbuf + wb4_off;
        const uint32_t wb4_lo = wb4_hi + WSPLIT;
        const uint32_t wb_hi6 = wbuf + wb_off + 6 * 1152;
        const uint32_t wb_lo6 = wb_hi6 + WSPLIT;

        uint32_t arow0 = (uint32_t)(((pyA0 + dy) * 10 + pxA0 + dx) * 144) + a_half;
        uint32_t arow1 = (uint32_t)(((((pA0 + 16) >> 3) + dy) * 10 + ((pA0 + 16) & 7) + dx) * 144) + a_half;

#pragma unroll
        for (int ks = 0; ks < 4; ks++) {
            const uint32_t ko = (uint32_t)(ks << 5);
            uint32_t Ah[2][4], Al[2][4];
            ldsm_x4(Ah[0][0], Ah[0][1], Ah[0][2], Ah[0][3], smb + SM_ACT_HI + arow0 + ko);
            ldsm_x4(Ah[1][0], Ah[1][1], Ah[1][2], Ah[1][3], smb + SM_ACT_HI + arow1 + ko);
            ldsm_x4(Al[0][0], Al[0][1], Al[0][2], Al[0][3], smb + SM_ACT_LO + arow0 + ko);
            ldsm_x4(Al[1][0], Al[1][1], Al[1][2], Al[1][3], smb + SM_ACT_LO + arow1 + ko);
#pragma unroll
            for (int pr = 0; pr < 3; pr++) {
                uint32_t bh[4], bl[4];
                ldsm_x4(bh[0], bh[1], bh[2], bh[3], wb4_hi + (uint32_t)(pr * 2304) + ko);
                ldsm_x4(bl[0], bl[1], bl[2], bl[3], wb4_lo + (uint32_t)(pr * 2304) + ko);
#pragma unroll
                for (int hfl = 0; hfl < 2; hfl++) {
                    const int nb = pr * 2 + hfl;
#pragma unroll
                    for (int mb = 0; mb < 2; mb++) {
                        mma16816(acc[mb][nb], Ah[mb], bh[2 * hfl], bh[2 * hfl + 1]);
                        mma16816(acc[mb][nb], Ah[mb], bl[2 * hfl], bl[2 * hfl + 1]);
                        mma16816(acc[mb][nb], Al[mb], bh[2 * hfl], bh[2 * hfl + 1]);
                    }
                }
            }
            {
                uint32_t bh0, bh1, bl0, bl1;
                ldsm_x2(bh0, bh1, wb_hi6 + ko);
                ldsm_x2(bl0, bl1, wb_lo6 + ko);
#pragma unroll
                for (int mb = 0; mb < 2; mb++) {
                    mma16816(acc[mb][6], Ah[mb], bh0, bh1);
                    mma16816(acc[mb][6], Ah[mb], bl0, bl1);
                    mma16816(acc[mb][6], Al[mb], bh0, bh1);
                }
            }
        }
    }
    __syncthreads();

    float* Dt = (float*)sm;
#pragma unroll
    for (int mb = 0; mb < 2; mb++) {
        int r = warpm * 32 + mb * 16 + (lan >> 2);
#pragma unroll
        for (int nb = 0; nb < 7; nb++) {
            int c = warpn * 56 + nb * 8 + 2 * (lan & 3);
            *(float2*)&Dt[r * DT_STRIDE + c] = make_float2(acc[mb][nb][0], acc[mb][nb][1]);
            *(float2*)&Dt[(r + 8) * DT_STRIDE + c] = make_float2(acc[mb][nb][2], acc[mb][nb][3]);
        }
    }
    __syncthreads();

    const float* scs = (const float*)(sm + SM_SCS);
    const float* bis = (const float*)(sm + SM_BIS);
    for (int it = tid; it < 512; it += 256) {
        int p = it >> 2, q = it & 3;
        float v[25];
        float mx = -1e30f;
#pragma unroll
        for (int k = 0; k < 25; k++) {
            int m = (k << 2) + q;
            float x = Dt[p * DT_STRIDE + m] * scs[m] + bis[m];
            v[k] = x;
            mx = fmaxf(mx, x);
        }
        float s = 0.f;
#pragma unroll
        for (int k = 0; k < 25; k++) {
            float e = __expf(v[k] - mx);
            v[k] = e;
            s += e;
        }
        float inv = 1.f / s;
        int y = 2 * (h0 + (p >> 3)) + (q >> 1);
        int x = 2 * (w0 + (p & 7)) + (q & 1);
#pragma unroll
        for (int k = 0; k < 25; k++)
            g_wm[(((size_t)(b * K2T + k)) * HO + y) * WO + x] = v[k] * inv;
    }
}

// ---------------------------------------------------------------------------
// K3 v10: v5 pipeline (double-buffered cp.async, one sync/cg) with 512
// threads: thread = (pixel, ch-group-of-4). Half the LDS instructions at
// identical crossbar bytes; 8 u64 accumulators.
// ---------------------------------------------------------------------------
#define XST 36
#define K3_WS   0
#define K3_XS0  25600
#define K3_XS1  46336
#define K3_SMEM 67072

__global__ __launch_bounds__(512, 3) void k3_carafe(float* __restrict__ out)
{
    extern __shared__ __align__(16) char sm3[];
    float* Ws4 = (float*)(sm3 + K3_WS);

    const int b = blockIdx.y;
    const int h0 = (blockIdx.x / 10) * 8;
    const int w0 = (blockIdx.x % 10) * 8;
    const int tid = threadIdx.x;

    for (int i = tid; i < 3200; i += 512) {
        int kk = i >> 7, r = i & 127, si = r >> 6, p = r & 63;
        int hh = p >> 3, ww = p & 7;
        int y = 2 * (h0 + hh) + si, x = 2 * (w0 + ww);
        float2 v = *(const float2*)&g_wm[(((size_t)(b * K2T + kk)) * HO + y) * WO + x];
        Ws4[(kk * 64 + p) * 4 + si * 2 + 0] = v.x;
        Ws4[(kk * 64 + p) * 4 + si * 2 + 1] = v.y;
    }

    const float* Xb = g_xT + (size_t)b * 6400 * 256;

#define K3_STAGE(cgx, bufoff) do {                                               \
        for (int i = tid; i < 1152; i += 512) {                                  \
            int pos = i >> 3, c16 = i & 7;                                       \
            int dy = pos / 12, dx = pos - dy * 12;                               \
            int gh = h0 + dy - 2, gw = w0 + dx - 2;                              \
            bool ok = (gh >= 0 && gh < HH && gw >= 0 && gw < WW);                \
            const float* src = Xb + (size_t)(ok ? (gh * WW + gw) : 0) * 256      \
                               + (cgx) * 32 + c16 * 4;                           \
            cp_async16(smem_u32(sm3 + (bufoff)) + (uint32_t)((pos * XST + c16 * 4) * 4), \
                       src, ok ? 16u : 0u);                                      \
        }                                                                        \
        asm volatile("cp.async.commit_group;" ::: "memory");                     \
    } while (0)

    K3_STAGE(0, K3_XS0);

    const int px = tid >> 3, cg8 = tid & 7;   // 64 px, 8 ch-groups of 4
    const int h = px >> 3, w = px & 7;
    const uint32_t xoff = (uint32_t)(((h * 12 + w) * XST + cg8 * 4) * 4);
    const uint32_t wbase = smem_u32(sm3) + (uint32_t)(px * 16);
    const int y0 = 2 * (h0 + h), x0 = 2 * (w0 + w);

    for (int cg = 0; cg < 8; cg++) {
        asm volatile("cp.async.wait_group 0;" ::: "memory");
        __syncthreads();
        if (cg + 1 < 8) {
            if ((cg + 1) & 1) K3_STAGE(cg + 1, K3_XS1);
            else              K3_STAGE(cg + 1, K3_XS0);
        }

        const uint32_t xb = smem_u32(sm3) + (uint32_t)((cg & 1) ? K3_XS1 : K3_XS0) + xoff;
        uint64_t acc[4][2];
#pragma unroll
        for (int s = 0; s < 4; s++) {
            acc[s][0] = 0ull;
            acc[s][1] = 0ull;
        }

#pragma unroll
        for (int t = 0; t < 25; t++) {
            const int ki = t / 5, kj = t - ki * 5;
            const uint32_t off = (uint32_t)((ki * 12 + kj) * XST * 4);
            float4 wv;
            asm volatile("ld.shared.v4.f32 {%0,%1,%2,%3}, [%4];"
                         : "=f"(wv.x), "=f"(wv.y), "=f"(wv.z), "=f"(wv.w)
                         : "r"(wbase + (uint32_t)(t * 1024)));
            uint64_t xq0, xq1;
            lds_v2u64(xq0, xq1, xb + off);
            uint64_t w2;
            w2 = bcast2(wv.x);
            fma2(acc[0][0], xq0, w2); fma2(acc[0][1], xq1, w2);
            w2 = bcast2(wv.y);
            fma2(acc[1][0], xq0, w2); fma2(acc[1][1], xq1, w2);
            w2 = bcast2(wv.z);
            fma2(acc[2][0], xq0, w2); fma2(acc[2][1], xq1, w2);
            w2 = bcast2(wv.w);
            fma2(acc[3][0], xq0, w2); fma2(acc[3][1], xq1, w2);
        }

        float* ob = out + (((size_t)(b * CIN + cg * 32 + cg8 * 4)) * HO + y0) * WO + x0;
#pragma unroll
        for (int k = 0; k < 2; k++) {
            float s0a, s0b, s1a, s1b, s2a, s2b, s3a, s3b;
            unpack2(s0a, s0b, acc[0][k]);
            unpack2(s1a, s1b, acc[1][k]);
            unpack2(s2a, s2b, acc[2][k]);
            unpack2(s3a, s3b, acc[3][k]);
            float* p0 = ob + (size_t)(2 * k) * (HO * WO);
            float* p1 = p0 + HO * WO;
            *(float2*)p0        = make_float2(s0a, s1a);
            *(float2*)(p0 + WO) = make_float2(s2a, s3a);
            *(float2*)p1        = make_float2(s0b, s1b);
            *(float2*)(p1 + WO) = make_float2(s2b, s3b);
        }
    }
}

// ---------------------------------------------------------------------------
extern "C" void kernel_launch(void* const* d_in, const int* in_sizes, int n_in,
                              void* d_out, int out_size)
{
    const float* X  = (const float*)d_in[0];
    const float* Wc = (const float*)d_in[1];
    const float* g1 = (const float*)d_in[2];
    const float* b1 = (const float*)d_in[3];
    const float* m1 = (const float*)d_in[4];
    const float* v1 = (const float*)d_in[5];
    const float* We = (const float*)d_in[6];
    const float* g2 = (const float*)d_in[7];
    const float* b2 = (const float*)d_in[8];
    const float* m2 = (const float*)d_in[9];
    const float* v2 = (const float*)d_in[10];
    float* out = (float*)d_out;

    cudaFuncSetAttribute(k1_comp, cudaFuncAttributeMaxDynamicSharedMemorySize, K1_SMEM);
    cudaFuncSetAttribute(k2_enc, cudaFuncAttributeMaxDynamicSharedMemorySize, SM_TOTAL);
    cudaFuncSetAttribute(k3_carafe, cudaFuncAttributeMaxDynamicSharedMemorySize, K3_SMEM);

    k0_wprep<<<527, 256>>>(We);
    k1_comp<<<dim3(50, BATCH), 256, K1_SMEM>>>(X, Wc, g1, b1, m1, v1);
    k2_enc<<<dim3(10, 5, BATCH), 256, SM_TOTAL>>>(g2, b2, m2, v2);
    k3_carafe<<<dim3(100, BATCH), 512, K3_SMEM>>>(out);
}

// round 16
// speedup vs baseline: 1.1605x; 1.1605x over previous
#include <cuda_runtime.h>
#include <cuda_bf16.h>
#include <cstdint>

#define BATCH 16
#define CIN   256
#define HH    80
#define WW    80
#define CMID  64
#define K2T   25
#define HO    160
#define WO    160
#define EPS   1e-5f

// ---------------------------------------------------------------------------
// Device scratch (allocation-free)
// ---------------------------------------------------------------------------
__device__ __align__(16) __nv_bfloat16 g_midT_hi[(size_t)BATCH * 6400 * 64]; // [b][pix][c]
__device__ __align__(16) __nv_bfloat16 g_midT_lo[(size_t)BATCH * 6400 * 64];
// per-tap weights, n-major: [tap][split][c(104)][ic(72)] bf16
__device__ __align__(16) __nv_bfloat16 g_weP[9 * 2 * 104 * 72];
__device__ __align__(16) float g_wm[(size_t)BATCH * K2T * HO * WO];
__device__ __align__(16) float g_xT[(size_t)BATCH * 6400 * 256];   // X pixel-major, 105MB

__device__ __forceinline__ uint32_t smem_u32(const void* p) {
    uint32_t a;
    asm("{ .reg .u64 t; cvta.to.shared.u64 t, %1; cvt.u32.u64 %0, t; }" : "=r"(a) : "l"(p));
    return a;
}
__device__ __forceinline__ void ldsm_x4(uint32_t& r0, uint32_t& r1, uint32_t& r2, uint32_t& r3,
                                        uint32_t addr) {
    asm volatile("ldmatrix.sync.aligned.m8n8.x4.shared.b16 {%0,%1,%2,%3}, [%4];"
                 : "=r"(r0), "=r"(r1), "=r"(r2), "=r"(r3) : "r"(addr));
}
__device__ __forceinline__ void ldsm_x2(uint32_t& r0, uint32_t& r1, uint32_t addr) {
    asm volatile("ldmatrix.sync.aligned.m8n8.x2.shared.b16 {%0,%1}, [%2];"
                 : "=r"(r0), "=r"(r1) : "r"(addr));
}
__device__ __forceinline__ void ldsm_x2t(uint32_t& r0, uint32_t& r1, uint32_t addr) {
    asm volatile("ldmatrix.sync.aligned.m8n8.x2.trans.shared.b16 {%0,%1}, [%2];"
                 : "=r"(r0), "=r"(r1) : "r"(addr));
}
__device__ __forceinline__ void mma16816(float* d, const uint32_t* a, uint32_t b0, uint32_t b1) {
    asm volatile(
        "mma.sync.aligned.m16n8k16.row.col.f32.bf16.bf16.f32 "
        "{%0,%1,%2,%3}, {%4,%5,%6,%7}, {%8,%9}, {%0,%1,%2,%3};"
        : "+f"(d[0]), "+f"(d[1]), "+f"(d[2]), "+f"(d[3])
        : "r"(a[0]), "r"(a[1]), "r"(a[2]), "r"(a[3]), "r"(b0), "r"(b1));
}
// Packed fp32 helpers (Blackwell f32x2 pipe)
__device__ __forceinline__ void fma2(uint64_t& d, uint64_t a, uint64_t b) {
    asm("fma.rn.f32x2 %0, %1, %2, %0;" : "+l"(d) : "l"(a), "l"(b));
}
__device__ __forceinline__ uint64_t bcast2(float x) {
    uint64_t r;
    asm("mov.b64 %0, {%1, %1};" : "=l"(r) : "f"(x));
    return r;
}
__device__ __forceinline__ void unpack2(float& lo, float& hi, uint64_t v) {
    asm("mov.b64 {%0, %1}, %2;" : "=f"(lo), "=f"(hi) : "l"(v));
}
__device__ __forceinline__ void lds_v2u64(uint64_t& a, uint64_t& b, uint32_t addr) {
    asm volatile("ld.shared.v2.u64 {%0, %1}, [%2];" : "=l"(a), "=l"(b) : "r"(addr));
}
__device__ __forceinline__ void cp_async16(uint32_t saddr, const void* gptr, uint32_t sz) {
    asm volatile("cp.async.cg.shared.global [%0], [%1], 16, %2;"
                 :: "r"(saddr), "l"(gptr), "r"(sz) : "memory");
}

// ---------------------------------------------------------------------------
// K0: conv2 weights -> [tap][split][c pad 104][ic pad 72] bf16 split
// ---------------------------------------------------------------------------
__global__ __launch_bounds__(256) void k0_wprep(const float* __restrict__ We) {
    int i = blockIdx.x * 256 + threadIdx.x;
    if (i >= 9 * 2 * 104 * 72) return;
    int tap = i / 14976, r = i % 14976;
    int s = r / 7488; r %= 7488;
    int c = r / 72, ic = r % 72;
    float v = (c < 100 && ic < 64) ? We[c * 576 + ic * 9 + tap] : 0.f;
    __nv_bfloat16 hi = __float2bfloat16(v);
    g_weP[i] = s ? __float2bfloat16(v - __bfloat162float(hi)) : hi;
}

// ---------------------------------------------------------------------------
// K1 v4: 1x1 conv (256->64) via mma.sync bf16 split-3 + BN + SiLU.
// Also writes fp32 X transpose g_xT. Prefetch issued BEFORE g_xT writeout.
// ---------------------------------------------------------------------------
#define K1_SW    0            // weights hi [64][528B] = 33792; lo at +33792
#define K1_SXS   67584        // X chunk bf16 [split][32k][272B] = 8704*2
#define K1_SBN   84992        // scs 256B + bis 256B
#define K1_XT32  85504        // fp32 transpose buffer [128px][36f] = 18432B
#define K1_SMEM  103936
#define K1_DT    0            // epilogue [split][128px][144B], reuses weights

__global__ __launch_bounds__(256, 2) void k1_comp(
    const float* __restrict__ X, const float* __restrict__ Wc,
    const float* __restrict__ g1, const float* __restrict__ b1,
    const float* __restrict__ m1, const float* __restrict__ v1)
{
    extern __shared__ __align__(16) char sm1[];
    const int b   = blockIdx.y;
    const int px0 = blockIdx.x * 128;
    const int tid = threadIdx.x;
    const int wid = tid >> 5, lan = tid & 31;
    const uint32_t smb = smem_u32(sm1);

    __nv_bfloat16* Wh = (__nv_bfloat16*)(sm1 + K1_SW);
    __nv_bfloat16* Wl = Wh + 16896;
    for (int i = tid; i < 16384; i += 256) {
        int m = i >> 8, k = i & 255;
        float v = Wc[i];
        __nv_bfloat16 hi = __float2bfloat16(v);
        Wh[m * 264 + k] = hi;
        Wl[m * 264 + k] = __float2bfloat16(v - __bfloat162float(hi));
    }
    float* scs = (float*)(sm1 + K1_SBN);
    float* bis = scs + 64;
    if (tid < 64) {
        float is = g1[tid] * rsqrtf(v1[tid] + EPS);
        scs[tid] = is;
        bis[tid] = b1[tid] - m1[tid] * is;
    }

    const float* Xb = X + (size_t)b * 256 * 6400 + px0;
    __nv_bfloat16* Xh = (__nv_bfloat16*)(sm1 + K1_SXS);
    __nv_bfloat16* Xl = Xh + 4352;
    float* XT = (float*)(sm1 + K1_XT32);

    float xp[16];
#pragma unroll
    for (int j = 0; j < 16; j++) {
        int e = j * 256 + tid;
        xp[j] = Xb[(size_t)(e >> 7) * 6400 + (e & 127)];
    }

    const int warpm = wid & 1;
    const int warpn = wid >> 1;

    float acc[2][4][4];
#pragma unroll
    for (int mb = 0; mb < 2; mb++)
#pragma unroll
        for (int nb = 0; nb < 4; nb++)
#pragma unroll
            for (int j = 0; j < 4; j++) acc[mb][nb][j] = 0.f;

    const uint32_t a_row = (uint32_t)(warpm * 32 + (lan & 15));
    const uint32_t a_half = (uint32_t)((lan >> 4) << 4);
    const uint32_t aw_hi = smb + K1_SW + a_row * 528 + a_half;
    const uint32_t aw_lo = aw_hi + 33792;
    const uint32_t b_base = smb + K1_SXS + (uint32_t)((lan & 15) * 272 + warpn * 64);

#pragma unroll 1
    for (int cg = 0; cg < 8; cg++) {
#pragma unroll
        for (int j = 0; j < 16; j++) {
            int e = j * 256 + tid;
            int kr = e >> 7, px = e & 127;
            float v = xp[j];
            __nv_bfloat16 hi = __float2bfloat16(v);
            Xh[kr * 136 + px] = hi;
            Xl[kr * 136 + px] = __float2bfloat16(v - __bfloat162float(hi));
            XT[px * 36 + kr] = v;
        }
        __syncthreads();

        // prefetch next chunk FIRST (independent LDGs fly during writeout)
        float xn[16];
        if (cg < 7) {
#pragma unroll
            for (int j = 0; j < 16; j++) {
                int e = j * 256 + tid;
                xn[j] = Xb[(size_t)((cg + 1) * 32 + (e >> 7)) * 6400 + (e & 127)];
            }
        }

        // write-out g_xT for this chunk (coalesced float4)
        {
            float* dst = g_xT + ((size_t)(b * 6400 + px0)) * 256 + cg * 32;
            for (int i = tid; i < 1024; i += 256) {
                int px = i >> 3, c4 = i & 7;
                float4 v = *(float4*)&XT[px * 36 + c4 * 4];
                *(float4*)&dst[(size_t)px * 256 + c4 * 4] = v;
            }
        }

        const uint32_t kco = (uint32_t)(cg * 64);
#pragma unroll
        for (int kstep = 0; kstep < 2; kstep++) {
            const uint32_t ko = kco + (uint32_t)(kstep * 32);
            uint32_t Ah[2][4], Al[2][4];
            ldsm_x4(Ah[0][0], Ah[0][1], Ah[0][2], Ah[0][3], aw_hi + ko);
            ldsm_x4(Ah[1][0], Ah[1][1], Ah[1][2], Ah[1][3], aw_hi + 16 * 528 + ko);
            ldsm_x4(Al[0][0], Al[0][1], Al[0][2], Al[0][3], aw_lo + ko);
            ldsm_x4(Al[1][0], Al[1][1], Al[1][2], Al[1][3], aw_lo + 16 * 528 + ko);
            const uint32_t bk = b_base + (uint32_t)(kstep * 16 * 272);
#pragma unroll
            for (int nb = 0; nb < 4; nb++) {
                uint32_t bh0, bh1, bl0, bl1;
                ldsm_x2t(bh0, bh1, bk + (uint32_t)(nb * 16));
                ldsm_x2t(bl0, bl1, bk + 8704 + (uint32_t)(nb * 16));
#pragma unroll
                for (int mb = 0; mb < 2; mb++) {
                    mma16816(acc[mb][nb], Ah[mb], bh0, bh1);
                    mma16816(acc[mb][nb], Ah[mb], bl0, bl1);
                    mma16816(acc[mb][nb], Al[mb], bh0, bh1);
                }
            }
        }
        __syncthreads();
#pragma unroll
        for (int j = 0; j < 16; j++) xp[j] = xn[j];
    }

    __nv_bfloat16* Dh = (__nv_bfloat16*)(sm1 + K1_DT);
    __nv_bfloat16* Dl = Dh + 9216;
#pragma unroll
    for (int mb = 0; mb < 2; mb++) {
#pragma unroll
        for (int nb = 0; nb < 4; nb++) {
            int m = warpm * 32 + mb * 16 + (lan >> 2);
            int p = warpn * 32 + nb * 8 + 2 * (lan & 3);
#pragma unroll
            for (int j = 0; j < 4; j++) {
                int mch = m + (j >> 1) * 8;
                int pp  = p + (j & 1);
                float v = acc[mb][nb][j] * scs[mch] + bis[mch];
                float sv = v / (1.f + __expf(-v));
                __nv_bfloat16 hi = __float2bfloat16(sv);
                Dh[pp * 72 + mch] = hi;
                Dl[pp * 72 + mch] = __float2bfloat16(sv - __bfloat162float(hi));
            }
        }
    }
    __syncthreads();

    for (int i = tid; i < 2048; i += 256) {
        int split = i >> 10, r = (i >> 3) & 127, ch8 = i & 7;
        uint4 v = *(const uint4*)(sm1 + K1_DT + split * 18432 + r * 144 + ch8 * 16);
        uint4* dst = (uint4*)(split ? g_midT_lo : g_midT_hi);
        dst[(size_t)(b * 6400 + px0 + r) * 8 + ch8] = v;
    }
}

// ---------------------------------------------------------------------------
// K2 v4: 3x3 conv via mma.sync bf16 split-3; cp.async for BOTH activations
// and double-buffered weights; ONE sync per tap; x4 B loads.
// ---------------------------------------------------------------------------
#define SM_ACT_HI 0
#define SM_ACT_LO 25920
#define SM_WB0    51840
#define SM_WB1    81792
#define SM_SCS    113472
#define SM_BIS    113872
#define SM_TOTAL  114272
#define WSPLIT    14976
#define DT_STRIDE 122

__global__ __launch_bounds__(256, 2)
void k2_enc(const float* __restrict__ g2, const float* __restrict__ b2,
            const float* __restrict__ m2, const float* __restrict__ v2)
{
    extern __shared__ __align__(16) char sm[];
    const int b  = blockIdx.z;
    const int h0 = blockIdx.y * 16;
    const int w0 = blockIdx.x * 8;
    const int tid = threadIdx.x;
    const int wid = tid >> 5;
    const int lan = tid & 31;
    const uint32_t smb = smem_u32(sm);

    if (tid < 100) {
        float is = g2[tid] * rsqrtf(v2[tid] + EPS);
        ((float*)(sm + SM_SCS))[tid] = is;
        ((float*)(sm + SM_BIS))[tid] = b2[tid] - m2[tid] * is;
    }

    // stage 18x10 activation tile (hi+lo) via cp.async (zfill borders)
    for (int k = tid; k < 2880; k += 256) {
        int bufi = (k >= 1440);
        int r = bufi ? k - 1440 : k;
        int row = r >> 3, ch = r & 7;
        int y = row / 10, x = row - y * 10;
        int gh = h0 + y - 1, gw = w0 + x - 1;
        bool ok = (gh >= 0 && gh < HH && gw >= 0 && gw < WW);
        const uint4* src = (const uint4*)(bufi ? g_midT_lo : g_midT_hi)
                           + (size_t)(b * 6400 + (ok ? (gh * WW + gw) : 0)) * 8 + ch;
        cp_async16(smb + (bufi ? SM_ACT_LO : SM_ACT_HI) + (uint32_t)(row * 144 + (ch << 4)),
                   src, ok ? 16u : 0u);
    }
    asm volatile("cp.async.commit_group;" ::: "memory");

#define K2_WSTAGE(tapx, bufoff) do {                                          \
        const uint4* gsrc = (const uint4*)g_weP + (tapx) * 1872;              \
        for (int k = tid; k < 1872; k += 256)                                 \
            cp_async16(smb + (bufoff) + (uint32_t)(k << 4), gsrc + k, 16);    \
        asm volatile("cp.async.commit_group;" ::: "memory");                  \
    } while (0)

    K2_WSTAGE(0, SM_WB0);

    const int warpm = wid & 3;
    const int warpn = wid >> 2;

    float acc[2][7][4];
#pragma unroll
    for (int mb = 0; mb < 2; mb++)
#pragma unroll
        for (int nb = 0; nb < 7; nb++)
#pragma unroll
            for (int j = 0; j < 4; j++) acc[mb][nb][j] = 0.f;

    const int pA0 = warpm * 32 + (lan & 15);
    const int pyA0 = pA0 >> 3, pxA0 = pA0 & 7;
    const uint32_t a_half = (uint32_t)((lan >> 4) << 4);
    const uint32_t row4 = (uint32_t)((lan & 7) + ((lan >> 4) << 3));
    const uint32_t half4 = (uint32_t)(((lan >> 3) & 1) << 4);
    const uint32_t wb4_off = ((uint32_t)warpn * 56 + row4) * 144 + half4;
    const int cB = warpn * 56 + (lan & 7);
    const uint32_t b_half = (uint32_t)(((lan >> 3) & 1) << 4);
    const uint32_t wb_off = (uint32_t)cB * 144 + b_half;

    for (int tap = 0; tap < 9; tap++) {
        const int dy = tap / 3, dx = tap - dy * 3;
        asm volatile("cp.async.wait_group 0;" ::: "memory");
        __syncthreads();
        if (tap + 1 < 9) {
            if ((tap + 1) & 1) K2_WSTAGE(tap + 1, SM_WB1);
            else               K2_WSTAGE(tap + 1, SM_WB0);
        }

        const uint32_t wbuf = smb + ((tap & 1) ? SM_WB1 : SM_WB0);
        const uint32_t wb4_hi = wbuf + wb4_off;
        const uint32_t wb4_lo = wb4_hi + WSPLIT;
        const uint32_t wb_hi6 = wbuf + wb_off + 6 * 1152;
        const uint32_t wb_lo6 = wb_hi6 + WSPLIT;

        uint32_t arow0 = (uint32_t)(((pyA0 + dy) * 10 + pxA0 + dx) * 144) + a_half;
        uint32_t arow1 = (uint32_t)(((((pA0 + 16) >> 3) + dy) * 10 + ((pA0 + 16) & 7) + dx) * 144) + a_half;

#pragma unroll
        for (int ks = 0; ks < 4; ks++) {
            const uint32_t ko = (uint32_t)(ks << 5);
            uint32_t Ah[2][4], Al[2][4];
            ldsm_x4(Ah[0][0], Ah[0][1], Ah[0][2], Ah[0][3], smb + SM_ACT_HI + arow0 + ko);
            ldsm_x4(Ah[1][0], Ah[1][1], Ah[1][2], Ah[1][3], smb + SM_ACT_HI + arow1 + ko);
            ldsm_x4(Al[0][0], Al[0][1], Al[0][2], Al[0][3], smb + SM_ACT_LO + arow0 + ko);
            ldsm_x4(Al[1][0], Al[1][1], Al[1][2], Al[1][3], smb + SM_ACT_LO + arow1 + ko);
#pragma unroll
            for (int pr = 0; pr < 3; pr++) {
                uint32_t bh[4], bl[4];
                ldsm_x4(bh[0], bh[1], bh[2], bh[3], wb4_hi + (uint32_t)(pr * 2304) + ko);
                ldsm_x4(bl[0], bl[1], bl[2], bl[3], wb4_lo + (uint32_t)(pr * 2304) + ko);
#pragma unroll
                for (int hfl = 0; hfl < 2; hfl++) {
                    const int nb = pr * 2 + hfl;
#pragma unroll
                    for (int mb = 0; mb < 2; mb++) {
                        mma16816(acc[mb][nb], Ah[mb], bh[2 * hfl], bh[2 * hfl + 1]);
                        mma16816(acc[mb][nb], Ah[mb], bl[2 * hfl], bl[2 * hfl + 1]);
                        mma16816(acc[mb][nb], Al[mb], bh[2 * hfl], bh[2 * hfl + 1]);
                    }
                }
            }
            {
                uint32_t bh0, bh1, bl0, bl1;
                ldsm_x2(bh0, bh1, wb_hi6 + ko);
                ldsm_x2(bl0, bl1, wb_lo6 + ko);
#pragma unroll
                for (int mb = 0; mb < 2; mb++) {
                    mma16816(acc[mb][6], Ah[mb], bh0, bh1);
                    mma16816(acc[mb][6], Ah[mb], bl0, bl1);
                    mma16816(acc[mb][6], Al[mb], bh0, bh1);
                }
            }
        }
    }
    __syncthreads();

    float* Dt = (float*)sm;
#pragma unroll
    for (int mb = 0; mb < 2; mb++) {
        int r = warpm * 32 + mb * 16 + (lan >> 2);
#pragma unroll
        for (int nb = 0; nb < 7; nb++) {
            int c = warpn * 56 + nb * 8 + 2 * (lan & 3);
            *(float2*)&Dt[r * DT_STRIDE + c] = make_float2(acc[mb][nb][0], acc[mb][nb][1]);
            *(float2*)&Dt[(r + 8) * DT_STRIDE + c] = make_float2(acc[mb][nb][2], acc[mb][nb][3]);
        }
    }
    __syncthreads();

    const float* scs = (const float*)(sm + SM_SCS);
    const float* bis = (const float*)(sm + SM_BIS);
    for (int it = tid; it < 512; it += 256) {
        int p = it >> 2, q = it & 3;
        float v[25];
        float mx = -1e30f;
#pragma unroll
        for (int k = 0; k < 25; k++) {
            int m = (k << 2) + q;
            float x = Dt[p * DT_STRIDE + m] * scs[m] + bis[m];
            v[k] = x;
            mx = fmaxf(mx, x);
        }
        float s = 0.f;
#pragma unroll
        for (int k = 0; k < 25; k++) {
            float e = __expf(v[k] - mx);
            v[k] = e;
            s += e;
        }
        float inv = 1.f / s;
        int y = 2 * (h0 + (p >> 3)) + (q >> 1);
        int x = 2 * (w0 + (p & 7)) + (q & 1);
#pragma unroll
        for (int k = 0; k < 25; k++)
            g_wm[(((size_t)(b * K2T + k)) * HO + y) * WO + x] = v[k] * inv;
    }
}

// ---------------------------------------------------------------------------
// K3 v5 (FROZEN converged config): thread = (pixel, ch-group-of-8),
// 4 subpixels/thread, double-buffered cp.async, one sync per cg.
// ---------------------------------------------------------------------------
#define XST 36
#define K3_WS   0
#define K3_XS0  25600
#define K3_XS1  46336
#define K3_SMEM 67072

__global__ __launch_bounds__(256, 3) void k3_carafe(float* __restrict__ out)
{
    extern __shared__ __align__(16) char sm3[];
    float* Ws4 = (float*)(sm3 + K3_WS);

    const int b = blockIdx.y;
    const int h0 = (blockIdx.x / 10) * 8;
    const int w0 = (blockIdx.x % 10) * 8;
    const int tid = threadIdx.x;

    for (int i = tid; i < 3200; i += 256) {
        int kk = i >> 7, r = i & 127, si = r >> 6, p = r & 63;
        int hh = p >> 3, ww = p & 7;
        int y = 2 * (h0 + hh) + si, x = 2 * (w0 + ww);
        float2 v = *(const float2*)&g_wm[(((size_t)(b * K2T + kk)) * HO + y) * WO + x];
        Ws4[(kk * 64 + p) * 4 + si * 2 + 0] = v.x;
        Ws4[(kk * 64 + p) * 4 + si * 2 + 1] = v.y;
    }

    const float* Xb = g_xT + (size_t)b * 6400 * 256;

#define K3_STAGE(cgx, bufoff) do {                                               \
        for (int i = tid; i < 1152; i += 256) {                                  \
            int pos = i >> 3, c16 = i & 7;                                       \
            int dy = pos / 12, dx = pos - dy * 12;                               \
            int gh = h0 + dy - 2, gw = w0 + dx - 2;                              \
            bool ok = (gh >= 0 && gh < HH && gw >= 0 && gw < WW);                \
            const float* src = Xb + (size_t)(ok ? (gh * WW + gw) : 0) * 256      \
                               + (cgx) * 32 + c16 * 4;                           \
            cp_async16(smem_u32(sm3 + (bufoff)) + (uint32_t)((pos * XST + c16 * 4) * 4), \
                       src, ok ? 16u : 0u);                                      \
        }                                                                        \
        asm volatile("cp.async.commit_group;" ::: "memory");                     \
    } while (0)

    K3_STAGE(0, K3_XS0);

    const int px = tid >> 2, cg4 = tid & 3;
    const int h = px >> 3, w = px & 7;
    const uint32_t xoff = (uint32_t)(((h * 12 + w) * XST + cg4 * 8) * 4);
    const uint32_t wbase = smem_u32(sm3) + (uint32_t)(px * 16);
    const int y0 = 2 * (h0 + h), x0 = 2 * (w0 + w);

    for (int cg = 0; cg < 8; cg++) {
        asm volatile("cp.async.wait_group 0;" ::: "memory");
        __syncthreads();
        if (cg + 1 < 8) {
            if ((cg + 1) & 1) K3_STAGE(cg + 1, K3_XS1);
            else              K3_STAGE(cg + 1, K3_XS0);
        }

        const uint32_t xb = smem_u32(sm3) + (uint32_t)((cg & 1) ? K3_XS1 : K3_XS0) + xoff;
        uint64_t acc[4][4];
#pragma unroll
        for (int s = 0; s < 4; s++)
#pragma unroll
            for (int k = 0; k < 4; k++) acc[s][k] = 0ull;

#pragma unroll
        for (int t = 0; t < 25; t++) {
            const int ki = t / 5, kj = t - ki * 5;
            const uint32_t off = (uint32_t)((ki * 12 + kj) * XST * 4);
            float4 wv;
            asm volatile("ld.shared.v4.f32 {%0,%1,%2,%3}, [%4];"
                         : "=f"(wv.x), "=f"(wv.y), "=f"(wv.z), "=f"(wv.w)
                         : "r"(wbase + (uint32_t)(t * 1024)));
            uint64_t w20 = bcast2(wv.x), w21 = bcast2(wv.y);
            uint64_t w22 = bcast2(wv.z), w23 = bcast2(wv.w);
            uint64_t xq0, xq1, xq2, xq3;
            lds_v2u64(xq0, xq1, xb + off);
            lds_v2u64(xq2, xq3, xb + off + 16);
            fma2(acc[0][0], xq0, w20); fma2(acc[0][1], xq1, w20);
            fma2(acc[0][2], xq2, w20); fma2(acc[0][3], xq3, w20);
            fma2(acc[1][0], xq0, w21); fma2(acc[1][1], xq1, w21);
            fma2(acc[1][2], xq2, w21); fma2(acc[1][3], xq3, w21);
            fma2(acc[2][0], xq0, w22); fma2(acc[2][1], xq1, w22);
            fma2(acc[2][2], xq2, w22); fma2(acc[2][3], xq3, w22);
            fma2(acc[3][0], xq0, w23); fma2(acc[3][1], xq1, w23);
            fma2(acc[3][2], xq2, w23); fma2(acc[3][3], xq3, w23);
        }

        float* ob = out + (((size_t)(b * CIN + cg * 32 + cg4 * 8)) * HO + y0) * WO + x0;
#pragma unroll
        for (int k = 0; k < 4; k++) {
            float s0a, s0b, s1a, s1b, s2a, s2b, s3a, s3b;
            unpack2(s0a, s0b, acc[0][k]);
            unpack2(s1a, s1b, acc[1][k]);
            unpack2(s2a, s2b, acc[2][k]);
            unpack2(s3a, s3b, acc[3][k]);
            float* p0 = ob + (size_t)(2 * k) * (HO * WO);
            float* p1 = p0 + HO * WO;
            *(float2*)p0        = make_float2(s0a, s1a);
            *(float2*)(p0 + WO) = make_float2(s2a, s3a);
            *(float2*)p1        = make_float2(s0b, s1b);
            *(float2*)(p1 + WO) = make_float2(s2b, s3b);
        }
    }
}

// ---------------------------------------------------------------------------
extern "C" void kernel_launch(void* const* d_in, const int* in_sizes, int n_in,
                              void* d_out, int out_size)
{
    const float* X  = (const float*)d_in[0];
    const float* Wc = (const float*)d_in[1];
    const float* g1 = (const float*)d_in[2];
    const float* b1 = (const float*)d_in[3];
    const float* m1 = (const float*)d_in[4];
    const float* v1 = (const float*)d_in[5];
    const float* We = (const float*)d_in[6];
    const float* g2 = (const float*)d_in[7];
    const float* b2 = (const float*)d_in[8];
    const float* m2 = (const float*)d_in[9];
    const float* v2 = (const float*)d_in[10];
    float* out = (float*)d_out;

    cudaFuncSetAttribute(k1_comp, cudaFuncAttributeMaxDynamicSharedMemorySize, K1_SMEM);
    cudaFuncSetAttribute(k2_enc, cudaFuncAttributeMaxDynamicSharedMemorySize, SM_TOTAL);
    cudaFuncSetAttribute(k3_carafe, cudaFuncAttributeMaxDynamicSharedMemorySize, K3_SMEM);

    k0_wprep<<<527, 256>>>(We);
    k1_comp<<<dim3(50, BATCH), 256, K1_SMEM>>>(X, Wc, g1, b1, m1, v1);
    k2_enc<<<dim3(10, 5, BATCH), 256, SM_TOTAL>>>(g2, b2, m2, v2);
    k3_carafe<<<dim3(100, BATCH), 256, K3_SMEM>>>(out);
}

// round 17
// speedup vs baseline: 1.1866x; 1.0224x over previous
#include <cuda_runtime.h>
#include <cuda_bf16.h>
#include <cstdint>

#define BATCH 16
#define CIN   256
#define HH    80
#define WW    80
#define CMID  64
#define K2T   25
#define HO    160
#define WO    160
#define EPS   1e-5f

// ---------------------------------------------------------------------------
// Device scratch (allocation-free)
// ---------------------------------------------------------------------------
__device__ __align__(16) __nv_bfloat16 g_midT_hi[(size_t)BATCH * 6400 * 64]; // [b][pix][c]
__device__ __align__(16) __nv_bfloat16 g_midT_lo[(size_t)BATCH * 6400 * 64];
// per-tap weights, n-major: [tap][split][c(104)][ic(72)] bf16
__device__ __align__(16) __nv_bfloat16 g_weP[9 * 2 * 104 * 72];
// CARAFE weights in K3-tile-blocked layout: [b][tile(100)][tap(25)][px(64)][s(4)]
__device__ __align__(16) float g_wm[(size_t)BATCH * 100 * K2T * 256];
__device__ __align__(16) float g_xT[(size_t)BATCH * 6400 * 256];   // X pixel-major, 105MB

__device__ __forceinline__ uint32_t smem_u32(const void* p) {
    uint32_t a;
    asm("{ .reg .u64 t; cvta.to.shared.u64 t, %1; cvt.u32.u64 %0, t; }" : "=r"(a) : "l"(p));
    return a;
}
__device__ __forceinline__ void ldsm_x4(uint32_t& r0, uint32_t& r1, uint32_t& r2, uint32_t& r3,
                                        uint32_t addr) {
    asm volatile("ldmatrix.sync.aligned.m8n8.x4.shared.b16 {%0,%1,%2,%3}, [%4];"
                 : "=r"(r0), "=r"(r1), "=r"(r2), "=r"(r3) : "r"(addr));
}
__device__ __forceinline__ void ldsm_x2(uint32_t& r0, uint32_t& r1, uint32_t addr) {
    asm volatile("ldmatrix.sync.aligned.m8n8.x2.shared.b16 {%0,%1}, [%2];"
                 : "=r"(r0), "=r"(r1) : "r"(addr));
}
__device__ __forceinline__ void ldsm_x2t(uint32_t& r0, uint32_t& r1, uint32_t addr) {
    asm volatile("ldmatrix.sync.aligned.m8n8.x2.trans.shared.b16 {%0,%1}, [%2];"
                 : "=r"(r0), "=r"(r1) : "r"(addr));
}
__device__ __forceinline__ void mma16816(float* d, const uint32_t* a, uint32_t b0, uint32_t b1) {
    asm volatile(
        "mma.sync.aligned.m16n8k16.row.col.f32.bf16.bf16.f32 "
        "{%0,%1,%2,%3}, {%4,%5,%6,%7}, {%8,%9}, {%0,%1,%2,%3};"
        : "+f"(d[0]), "+f"(d[1]), "+f"(d[2]), "+f"(d[3])
        : "r"(a[0]), "r"(a[1]), "r"(a[2]), "r"(a[3]), "r"(b0), "r"(b1));
}
// Packed fp32 helpers (Blackwell f32x2 pipe)
__device__ __forceinline__ void fma2(uint64_t& d, uint64_t a, uint64_t b) {
    asm("fma.rn.f32x2 %0, %1, %2, %0;" : "+l"(d) : "l"(a), "l"(b));
}
__device__ __forceinline__ uint64_t bcast2(float x) {
    uint64_t r;
    asm("mov.b64 %0, {%1, %1};" : "=l"(r) : "f"(x));
    return r;
}
__device__ __forceinline__ void unpack2(float& lo, float& hi, uint64_t v) {
    asm("mov.b64 {%0, %1}, %2;" : "=f"(lo), "=f"(hi) : "l"(v));
}
__device__ __forceinline__ void lds_v2u64(uint64_t& a, uint64_t& b, uint32_t addr) {
    asm volatile("ld.shared.v2.u64 {%0, %1}, [%2];" : "=l"(a), "=l"(b) : "r"(addr));
}
__device__ __forceinline__ void cp_async16(uint32_t saddr, const void* gptr, uint32_t sz) {
    asm volatile("cp.async.cg.shared.global [%0], [%1], 16, %2;"
                 :: "r"(saddr), "l"(gptr), "r"(sz) : "memory");
}

// ---------------------------------------------------------------------------
// K0: conv2 weights -> [tap][split][c pad 104][ic pad 72] bf16 split
// ---------------------------------------------------------------------------
__global__ __launch_bounds__(256) void k0_wprep(const float* __restrict__ We) {
    int i = blockIdx.x * 256 + threadIdx.x;
    if (i >= 9 * 2 * 104 * 72) return;
    int tap = i / 14976, r = i % 14976;
    int s = r / 7488; r %= 7488;
    int c = r / 72, ic = r % 72;
    float v = (c < 100 && ic < 64) ? We[c * 576 + ic * 9 + tap] : 0.f;
    __nv_bfloat16 hi = __float2bfloat16(v);
    g_weP[i] = s ? __float2bfloat16(v - __bfloat162float(hi)) : hi;
}

// ---------------------------------------------------------------------------
// K1 v3 (R13 order): 1x1 conv via mma.sync bf16 split-3 + BN + SiLU.
// Also writes the fp32 X transpose g_xT[b][px][c] from staged chunks.
// ---------------------------------------------------------------------------
#define K1_SW    0            // weights hi [64][528B] = 33792; lo at +33792
#define K1_SXS   67584        // X chunk bf16 [split][32k][272B] = 8704*2
#define K1_SBN   84992        // scs 256B + bis 256B
#define K1_XT32  85504        // fp32 transpose buffer [128px][36f] = 18432B
#define K1_SMEM  103936
#define K1_DT    0            // epilogue [split][128px][144B], reuses weights

__global__ __launch_bounds__(256, 2) void k1_comp(
    const float* __restrict__ X, const float* __restrict__ Wc,
    const float* __restrict__ g1, const float* __restrict__ b1,
    const float* __restrict__ m1, const float* __restrict__ v1)
{
    extern __shared__ __align__(16) char sm1[];
    const int b   = blockIdx.y;
    const int px0 = blockIdx.x * 128;
    const int tid = threadIdx.x;
    const int wid = tid >> 5, lan = tid & 31;
    const uint32_t smb = smem_u32(sm1);

    __nv_bfloat16* Wh = (__nv_bfloat16*)(sm1 + K1_SW);
    __nv_bfloat16* Wl = Wh + 16896;
    for (int i = tid; i < 16384; i += 256) {
        int m = i >> 8, k = i & 255;
        float v = Wc[i];
        __nv_bfloat16 hi = __float2bfloat16(v);
        Wh[m * 264 + k] = hi;
        Wl[m * 264 + k] = __float2bfloat16(v - __bfloat162float(hi));
    }
    float* scs = (float*)(sm1 + K1_SBN);
    float* bis = scs + 64;
    if (tid < 64) {
        float is = g1[tid] * rsqrtf(v1[tid] + EPS);
        scs[tid] = is;
        bis[tid] = b1[tid] - m1[tid] * is;
    }

    const float* Xb = X + (size_t)b * 256 * 6400 + px0;
    __nv_bfloat16* Xh = (__nv_bfloat16*)(sm1 + K1_SXS);
    __nv_bfloat16* Xl = Xh + 4352;
    float* XT = (float*)(sm1 + K1_XT32);

    float xp[16];
#pragma unroll
    for (int j = 0; j < 16; j++) {
        int e = j * 256 + tid;
        xp[j] = Xb[(size_t)(e >> 7) * 6400 + (e & 127)];
    }

    const int warpm = wid & 1;
    const int warpn = wid >> 1;

    float acc[2][4][4];
#pragma unroll
    for (int mb = 0; mb < 2; mb++)
#pragma unroll
        for (int nb = 0; nb < 4; nb++)
#pragma unroll
            for (int j = 0; j < 4; j++) acc[mb][nb][j] = 0.f;

    const uint32_t a_row = (uint32_t)(warpm * 32 + (lan & 15));
    const uint32_t a_half = (uint32_t)((lan >> 4) << 4);
    const uint32_t aw_hi = smb + K1_SW + a_row * 528 + a_half;
    const uint32_t aw_lo = aw_hi + 33792;
    const uint32_t b_base = smb + K1_SXS + (uint32_t)((lan & 15) * 272 + warpn * 64);

#pragma unroll 1
    for (int cg = 0; cg < 8; cg++) {
#pragma unroll
        for (int j = 0; j < 16; j++) {
            int e = j * 256 + tid;
            int kr = e >> 7, px = e & 127;
            float v = xp[j];
            __nv_bfloat16 hi = __float2bfloat16(v);
            Xh[kr * 136 + px] = hi;
            Xl[kr * 136 + px] = __float2bfloat16(v - __bfloat162float(hi));
            XT[px * 36 + kr] = v;
        }
        __syncthreads();

        {
            float* dst = g_xT + ((size_t)(b * 6400 + px0)) * 256 + cg * 32;
            for (int i = tid; i < 1024; i += 256) {
                int px = i >> 3, c4 = i & 7;
                float4 v = *(float4*)&XT[px * 36 + c4 * 4];
                *(float4*)&dst[(size_t)px * 256 + c4 * 4] = v;
            }
        }

        float xn[16];
        if (cg < 7) {
#pragma unroll
            for (int j = 0; j < 16; j++) {
                int e = j * 256 + tid;
                xn[j] = Xb[(size_t)((cg + 1) * 32 + (e >> 7)) * 6400 + (e & 127)];
            }
        }

        const uint32_t kco = (uint32_t)(cg * 64);
#pragma unroll
        for (int kstep = 0; kstep < 2; kstep++) {
            const uint32_t ko = kco + (uint32_t)(kstep * 32);
            uint32_t Ah[2][4], Al[2][4];
            ldsm_x4(Ah[0][0], Ah[0][1], Ah[0][2], Ah[0][3], aw_hi + ko);
            ldsm_x4(Ah[1][0], Ah[1][1], Ah[1][2], Ah[1][3], aw_hi + 16 * 528 + ko);
            ldsm_x4(Al[0][0], Al[0][1], Al[0][2], Al[0][3], aw_lo + ko);
            ldsm_x4(Al[1][0], Al[1][1], Al[1][2], Al[1][3], aw_lo + 16 * 528 + ko);
            const uint32_t bk = b_base + (uint32_t)(kstep * 16 * 272);
#pragma unroll
            for (int nb = 0; nb < 4; nb++) {
                uint32_t bh0, bh1, bl0, bl1;
                ldsm_x2t(bh0, bh1, bk + (uint32_t)(nb * 16));
                ldsm_x2t(bl0, bl1, bk + 8704 + (uint32_t)(nb * 16));
#pragma unroll
                for (int mb = 0; mb < 2; mb++) {
                    mma16816(acc[mb][nb], Ah[mb], bh0, bh1);
                    mma16816(acc[mb][nb], Ah[mb], bl0, bl1);
                    mma16816(acc[mb][nb], Al[mb], bh0, bh1);
                }
            }
        }
        __syncthreads();
#pragma unroll
        for (int j = 0; j < 16; j++) xp[j] = xn[j];
    }

    __nv_bfloat16* Dh = (__nv_bfloat16*)(sm1 + K1_DT);
    __nv_bfloat16* Dl = Dh + 9216;
#pragma unroll
    for (int mb = 0; mb < 2; mb++) {
#pragma unroll
        for (int nb = 0; nb < 4; nb++) {
            int m = warpm * 32 + mb * 16 + (lan >> 2);
            int p = warpn * 32 + nb * 8 + 2 * (lan & 3);
#pragma unroll
            for (int j = 0; j < 4; j++) {
                int mch = m + (j >> 1) * 8;
                int pp  = p + (j & 1);
                float v = acc[mb][nb][j] * scs[mch] + bis[mch];
                float sv = v / (1.f + __expf(-v));
                __nv_bfloat16 hi = __float2bfloat16(sv);
                Dh[pp * 72 + mch] = hi;
                Dl[pp * 72 + mch] = __float2bfloat16(sv - __bfloat162float(hi));
            }
        }
    }
    __syncthreads();

    for (int i = tid; i < 2048; i += 256) {
        int split = i >> 10, r = (i >> 3) & 127, ch8 = i & 7;
        uint4 v = *(const uint4*)(sm1 + K1_DT + split * 18432 + r * 144 + ch8 * 16);
        uint4* dst = (uint4*)(split ? g_midT_lo : g_midT_hi);
        dst[(size_t)(b * 6400 + px0 + r) * 8 + ch8] = v;
    }
}

// ---------------------------------------------------------------------------
// K2 v5: 3x3 conv via mma.sync bf16 split-3; cp.async staging; ONE sync/tap;
// x4 B loads. Epilogue writes g_wm in K3-tile-blocked layout (coalesced).
// ---------------------------------------------------------------------------
#define SM_ACT_HI 0
#define SM_ACT_LO 25920
#define SM_WB0    51840
#define SM_WB1    81792
#define SM_SCS    113472
#define SM_BIS    113872
#define SM_TOTAL  114272
#define WSPLIT    14976
#define DT_STRIDE 122

__global__ __launch_bounds__(256, 2)
void k2_enc(const float* __restrict__ g2, const float* __restrict__ b2,
            const float* __restrict__ m2, const float* __restrict__ v2)
{
    extern __shared__ __align__(16) char sm[];
    const int b  = blockIdx.z;
    const int by = blockIdx.y, bx = blockIdx.x;
    const int h0 = by * 16;
    const int w0 = bx * 8;
    const int tid = threadIdx.x;
    const int wid = tid >> 5;
    const int lan = tid & 31;
    const uint32_t smb = smem_u32(sm);

    if (tid < 100) {
        float is = g2[tid] * rsqrtf(v2[tid] + EPS);
        ((float*)(sm + SM_SCS))[tid] = is;
        ((float*)(sm + SM_BIS))[tid] = b2[tid] - m2[tid] * is;
    }

    // stage 18x10 activation tile (hi+lo) via cp.async (zfill borders)
    for (int k = tid; k < 2880; k += 256) {
        int bufi = (k >= 1440);
        int r = bufi ? k - 1440 : k;
        int row = r >> 3, ch = r & 7;
        int y = row / 10, x = row - y * 10;
        int gh = h0 + y - 1, gw = w0 + x - 1;
        bool ok = (gh >= 0 && gh < HH && gw >= 0 && gw < WW);
        const uint4* src = (const uint4*)(bufi ? g_midT_lo : g_midT_hi)
                           + (size_t)(b * 6400 + (ok ? (gh * WW + gw) : 0)) * 8 + ch;
        cp_async16(smb + (bufi ? SM_ACT_LO : SM_ACT_HI) + (uint32_t)(row * 144 + (ch << 4)),
                   src, ok ? 16u : 0u);
    }
    asm volatile("cp.async.commit_group;" ::: "memory");

#define K2_WSTAGE(tapx, bufoff) do {                                          \
        const uint4* gsrc = (const uint4*)g_weP + (tapx) * 1872;              \
        for (int k = tid; k < 1872; k += 256)                                 \
            cp_async16(smb + (bufoff) + (uint32_t)(k << 4), gsrc + k, 16);    \
        asm volatile("cp.async.commit_group;" ::: "memory");                  \
    } while (0)

    K2_WSTAGE(0, SM_WB0);

    const int warpm = wid & 3;
    const int warpn = wid >> 2;

    float acc[2][7][4];
#pragma unroll
    for (int mb = 0; mb < 2; mb++)
#pragma unroll
        for (int nb = 0; nb < 7; nb++)
#pragma unroll
            for (int j = 0; j < 4; j++) acc[mb][nb][j] = 0.f;

    const int pA0 = warpm * 32 + (lan & 15);
    const int pyA0 = pA0 >> 3, pxA0 = pA0 & 7;
    const uint32_t a_half = (uint32_t)((lan >> 4) << 4);
    const uint32_t row4 = (uint32_t)((lan & 7) + ((lan >> 4) << 3));
    const uint32_t half4 = (uint32_t)(((lan >> 3) & 1) << 4);
    const uint32_t wb4_off = ((uint32_t)warpn * 56 + row4) * 144 + half4;
    const int cB = warpn * 56 + (lan & 7);
    const uint32_t b_half = (uint32_t)(((lan >> 3) & 1) << 4);
    const uint32_t wb_off = (uint32_t)cB * 144 + b_half;

    for (int tap = 0; tap < 9; tap++) {
        const int dy = tap / 3, dx = tap - dy * 3;
        asm volatile("cp.async.wait_group 0;" ::: "memory");
        __syncthreads();
        if (tap + 1 < 9) {
            if ((tap + 1) & 1) K2_WSTAGE(tap + 1, SM_WB1);
            else               K2_WSTAGE(tap + 1, SM_WB0);
        }

        const uint32_t wbuf = smb + ((tap & 1) ? SM_WB1 : SM_WB0);
        const uint32_t wb4_hi = wbuf + wb4_off;
        const uint32_t wb4_lo = wb4_hi + WSPLIT;
        const uint32_t wb_hi6 = wbuf + wb_off + 6 * 1152;
        const uint32_t wb_lo6 = wb_hi6 + WSPLIT;

        uint32_t arow0 = (uint32_t)(((pyA0 + dy) * 10 + pxA0 + dx) * 144) + a_half;
        uint32_t arow1 = (uint32_t)(((((pA0 + 16) >> 3) + dy) * 10 + ((pA0 + 16) & 7) + dx) * 144) + a_half;

#pragma unroll
        for (int ks = 0; ks < 4; ks++) {
            const uint32_t ko = (uint32_t)(ks << 5);
            uint32_t Ah[2][4], Al[2][4];
            ldsm_x4(Ah[0][0], Ah[0][1], Ah[0][2], Ah[0][3], smb + SM_ACT_HI + arow0 + ko);
            ldsm_x4(Ah[1][0], Ah[1][1], Ah[1][2], Ah[1][3], smb + SM_ACT_HI + arow1 + ko);
            ldsm_x4(Al[0][0], Al[0][1], Al[0][2], Al[0][3], smb + SM_ACT_LO + arow0 + ko);
            ldsm_x4(Al[1][0], Al[1][1], Al[1][2], Al[1][3], smb + SM_ACT_LO + arow1 + ko);
#pragma unroll
            for (int pr = 0; pr < 3; pr++) {
                uint32_t bh[4], bl[4];
                ldsm_x4(bh[0], bh[1], bh[2], bh[3], wb4_hi + (uint32_t)(pr * 2304) + ko);
                ldsm_x4(bl[0], bl[1], bl[2], bl[3], wb4_lo + (uint32_t)(pr * 2304) + ko);
#pragma unroll
                for (int hfl = 0; hfl < 2; hfl++) {
                    const int nb = pr * 2 + hfl;
#pragma unroll
                    for (int mb = 0; mb < 2; mb++) {
                        mma16816(acc[mb][nb], Ah[mb], bh[2 * hfl], bh[2 * hfl + 1]);
                        mma16816(acc[mb][nb], Ah[mb], bl[2 * hfl], bl[2 * hfl + 1]);
                        mma16816(acc[mb][nb], Al[mb], bh[2 * hfl], bh[2 * hfl + 1]);
                    }
                }
            }
            {
                uint32_t bh0, bh1, bl0, bl1;
                ldsm_x2(bh0, bh1, wb_hi6 + ko);
                ldsm_x2(bl0, bl1, wb_lo6 + ko);
#pragma unroll
                for (int mb = 0; mb < 2; mb++) {
                    mma16816(acc[mb][6], Ah[mb], bh0, bh1);
                    mma16816(acc[mb][6], Ah[mb], bl0, bl1);
                    mma16816(acc[mb][6], Al[mb], bh0, bh1);
                }
            }
        }
    }
    __syncthreads();

    float* Dt = (float*)sm;
#pragma unroll
    for (int mb = 0; mb < 2; mb++) {
        int r = warpm * 32 + mb * 16 + (lan >> 2);
#pragma unroll
        for (int nb = 0; nb < 7; nb++) {
            int c = warpn * 56 + nb * 8 + 2 * (lan & 3);
            *(float2*)&Dt[r * DT_STRIDE + c] = make_float2(acc[mb][nb][0], acc[mb][nb][1]);
            *(float2*)&Dt[(r + 8) * DT_STRIDE + c] = make_float2(acc[mb][nb][2], acc[mb][nb][3]);
        }
    }
    __syncthreads();

    // BN + softmax; write g_wm in K3-tile-blocked layout:
    // g_wm[((b*100 + t3)*25 + k)*256 + px*4 + q], t3 = (2*by + (p>>6))*10 + bx
    const float* scs = (const float*)(sm + SM_SCS);
    const float* bis = (const float*)(sm + SM_BIS);
    for (int it = tid; it < 512; it += 256) {
        int p = it >> 2, q = it & 3;
        float v[25];
        float mx = -1e30f;
#pragma unroll
        for (int k = 0; k < 25; k++) {
            int m = (k << 2) + q;
            float x = Dt[p * DT_STRIDE + m] * scs[m] + bis[m];
            v[k] = x;
            mx = fmaxf(mx, x);
        }
        float s = 0.f;
#pragma unroll
        for (int k = 0; k < 25; k++) {
            float e = __expf(v[k] - mx);
            v[k] = e;
            s += e;
        }
        float inv = 1.f / s;
        const int t3 = (2 * by + (p >> 6)) * 10 + bx;
        float* wout = g_wm + ((size_t)(b * 100 + t3) * 25) * 256 + (p & 63) * 4 + q;
#pragma unroll
        for (int k = 0; k < 25; k++)
            wout[k * 256] = v[k] * inv;
    }
}

// ---------------------------------------------------------------------------
// K3 v5b (frozen v5 + contiguous cp.async weight staging, overlapped with
// chunk-0 X stage): thread = (pixel, ch-group-of-8), 4 subpixels/thread.
// ---------------------------------------------------------------------------
#define XST 36
#define K3_WS   0
#define K3_XS0  25600
#define K3_XS1  46336
#define K3_SMEM 67072

__global__ __launch_bounds__(256, 3) void k3_carafe(float* __restrict__ out)
{
    extern __shared__ __align__(16) char sm3[];

    const int b = blockIdx.y;
    const int h0 = (blockIdx.x / 10) * 8;
    const int w0 = (blockIdx.x % 10) * 8;
    const int tid = threadIdx.x;

    // weights: ONE contiguous 25600B cp.async copy (layout matches Ws4 exactly)
    {
        const uint4* wsrc = (const uint4*)(g_wm + ((size_t)(b * 100 + blockIdx.x) * 25) * 256);
        for (int i = tid; i < 1600; i += 256)
            cp_async16(smem_u32(sm3 + K3_WS) + (uint32_t)(i << 4), wsrc + i, 16);
    }

    const float* Xb = g_xT + (size_t)b * 6400 * 256;

#define K3_STAGE(cgx, bufoff) do {                                               \
        for (int i = tid; i < 1152; i += 256) {                                  \
            int pos = i >> 3, c16 = i & 7;                                       \
            int dy = pos / 12, dx = pos - dy * 12;                               \
            int gh = h0 + dy - 2, gw = w0 + dx - 2;                              \
            bool ok = (gh >= 0 && gh < HH && gw >= 0 && gw < WW);                \
            const float* src = Xb + (size_t)(ok ? (gh * WW + gw) : 0) * 256      \
                               + (cgx) * 32 + c16 * 4;                           \
            cp_async16(smem_u32(sm3 + (bufoff)) + (uint32_t)((pos * XST + c16 * 4) * 4), \
                       src, ok ? 16u : 0u);                                      \
        }                                                                        \
        asm volatile("cp.async.commit_group;" ::: "memory");                     \
    } while (0)

    K3_STAGE(0, K3_XS0);   // commit closes weight copies + chunk-0 into one group

    const int px = tid >> 2, cg4 = tid & 3;
    const int h = px >> 3, w = px & 7;
    const uint32_t xoff = (uint32_t)(((h * 12 + w) * XST + cg4 * 8) * 4);
    const uint32_t wbase = smem_u32(sm3) + (uint32_t)(px * 16);
    const int y0 = 2 * (h0 + h), x0 = 2 * (w0 + w);

    for (int cg = 0; cg < 8; cg++) {
        asm volatile("cp.async.wait_group 0;" ::: "memory");
        __syncthreads();
        if (cg + 1 < 8) {
            if ((cg + 1) & 1) K3_STAGE(cg + 1, K3_XS1);
            else              K3_STAGE(cg + 1, K3_XS0);
        }

        const uint32_t xb = smem_u32(sm3) + (uint32_t)((cg & 1) ? K3_XS1 : K3_XS0) + xoff;
        uint64_t acc[4][4];
#pragma unroll
        for (int s = 0; s < 4; s++)
#pragma unroll
            for (int k = 0; k < 4; k++) acc[s][k] = 0ull;

#pragma unroll
        for (int t = 0; t < 25; t++) {
            const int ki = t / 5, kj = t - ki * 5;
            const uint32_t off = (uint32_t)((ki * 12 + kj) * XST * 4);
            float4 wv;
            asm volatile("ld.shared.v4.f32 {%0,%1,%2,%3}, [%4];"
                         : "=f"(wv.x), "=f"(wv.y), "=f"(wv.z), "=f"(wv.w)
                         : "r"(wbase + (uint32_t)(t * 1024)));
            uint64_t w20 = bcast2(wv.x), w21 = bcast2(wv.y);
            uint64_t w22 = bcast2(wv.z), w23 = bcast2(wv.w);
            uint64_t xq0, xq1, xq2, xq3;
            lds_v2u64(xq0, xq1, xb + off);
            lds_v2u64(xq2, xq3, xb + off + 16);
            fma2(acc[0][0], xq0, w20); fma2(acc[0][1], xq1, w20);
            fma2(acc[0][2], xq2, w20); fma2(acc[0][3], xq3, w20);
            fma2(acc[1][0], xq0, w21); fma2(acc[1][1], xq1, w21);
            fma2(acc[1][2], xq2, w21); fma2(acc[1][3], xq3, w21);
            fma2(acc[2][0], xq0, w22); fma2(acc[2][1], xq1, w22);
            fma2(acc[2][2], xq2, w22); fma2(acc[2][3], xq3, w22);
            fma2(acc[3][0], xq0, w23); fma2(acc[3][1], xq1, w23);
            fma2(acc[3][2], xq2, w23); fma2(acc[3][3], xq3, w23);
        }

        float* ob = out + (((size_t)(b * CIN + cg * 32 + cg4 * 8)) * HO + y0) * WO + x0;
#pragma unroll
        for (int k = 0; k < 4; k++) {
            float s0a, s0b, s1a, s1b, s2a, s2b, s3a, s3b;
            unpack2(s0a, s0b, acc[0][k]);
            unpack2(s1a, s1b, acc[1][k]);
            unpack2(s2a, s2b, acc[2][k]);
            unpack2(s3a, s3b, acc[3][k]);
            float* p0 = ob + (size_t)(2 * k) * (HO * WO);
            float* p1 = p0 + HO * WO;
            *(float2*)p0        = make_float2(s0a, s1a);
            *(float2*)(p0 + WO) = make_float2(s2a, s3a);
            *(float2*)p1        = make_float2(s0b, s1b);
            *(float2*)(p1 + WO) = make_float2(s2b, s3b);
        }
    }
}

// ---------------------------------------------------------------------------
extern "C" void kernel_launch(void* const* d_in, const int* in_sizes, int n_in,
                              void* d_out, int out_size)
{
    const float* X  = (const float*)d_in[0];
    const float* Wc = (const float*)d_in[1];
    const float* g1 = (const float*)d_in[2];
    const float* b1 = (const float*)d_in[3];
    const float* m1 = (const float*)d_in[4];
    const float* v1 = (const float*)d_in[5];
    const float* We = (const float*)d_in[6];
    const float* g2 = (const float*)d_in[7];
    const float* b2 = (const float*)d_in[8];
    const float* m2 = (const float*)d_in[9];
    const float* v2 = (const float*)d_in[10];
    float* out = (float*)d_out;

    cudaFuncSetAttribute(k1_comp, cudaFuncAttributeMaxDynamicSharedMemorySize, K1_SMEM);
    cudaFuncSetAttribute(k2_enc, cudaFuncAttributeMaxDynamicSharedMemorySize, SM_TOTAL);
    cudaFuncSetAttribute(k3_carafe, cudaFuncAttributeMaxDynamicSharedMemorySize, K3_SMEM);

    k0_wprep<<<527, 256>>>(We);
    k1_comp<<<dim3(50, BATCH), 256, K1_SMEM>>>(X, Wc, g1, b1, m1, v1);
    k2_enc<<<dim3(10, 5, BATCH), 256, SM_TOTAL>>>(g2, b2, m2, v2);
    k3_carafe<<<dim3(100, BATCH), 256, K3_SMEM>>>(out);
}